// round 8
// baseline (speedup 1.0000x reference)
#include <cuda_runtime.h>
#include <cuda_fp16.h>
#include <cstdint>
#include <cstddef>

#define DI __device__ __forceinline__

static constexpr int Mdim = 8192, Ndim = 4096, Kdim = 4096;
static constexpr int MT = 256, NT = 128, KT = 32;
static constexpr int NKT = Kdim / KT;              // 128
static constexpr int ROWB = 96;                    // row stride bytes (64B data + 32B pad)
static constexpr int RP8 = ROWB / 8;               // 12
static constexpr int TILE_A = 256 * ROWB;          // 24576 B
static constexpr int TILE_B = 128 * ROWB;          // 12288 B
static constexpr int STG = TILE_A + TILE_B;        // 36864 B
static constexpr int NSTG = 5;
static constexpr unsigned SMEM_BYTES = NSTG * STG; // 184320

// fp16, k-interleaved within each 16-k group: word slots [k0k1 k8k9 k2k3 k10k11 k4k5 k12k13 k6k7 k14k15]
__device__ __half g_wt[(size_t)Ndim * Kdim];       // W^T [n][k]
__device__ __half g_a [(size_t)Mdim * Kdim];       // A   [m][k]

DI uint32_t smem_u32(const void* p) {
    uint32_t a;
    asm("{ .reg .u64 t; cvta.to.shared.u64 t, %1; cvt.u32.u64 %0, t; }" : "=r"(a) : "l"(p));
    return a;
}
DI void cpa16(uint32_t dst, const void* src) {
    asm volatile("cp.async.cg.shared.global [%0], [%1], 16;" :: "r"(dst), "l"(src) : "memory");
}
DI void cpa_commit() { asm volatile("cp.async.commit_group;" ::: "memory"); }
template <int N> DI void cpa_wait() {
    asm volatile("cp.async.wait_group %0;" :: "n"(N) : "memory");
}
DI void mma16(float* d, uint32_t a0, uint32_t a1, uint32_t a2, uint32_t a3,
              uint32_t b0, uint32_t b1) {
    asm volatile(
        "mma.sync.aligned.m16n8k16.row.col.f32.f16.f16.f32 "
        "{%0,%1,%2,%3}, {%4,%5,%6,%7}, {%8,%9}, {%0,%1,%2,%3};"
        : "+f"(d[0]), "+f"(d[1]), "+f"(d[2]), "+f"(d[3])
        : "r"(a0), "r"(a1), "r"(a2), "r"(a3), "r"(b0), "r"(b1));
}
DI int ileave16(int e) {
    int p = (e >> 1) & 7, o = e & 1;
    int slot = ((p & 3) << 1) | (p >> 2);
    return (e & ~15) | (slot << 1) | o;
}

// ---------- fused prep: W dequant+transpose+interleave, and A convert+interleave ----------
static constexpr int NWB = (Ndim / 32) * (Kdim / 32);   // 16384 W blocks
static constexpr int NAB = (int)((size_t)Mdim * Kdim / 16 / 256);  // 8192 A blocks

__global__ void prep_k(const int* __restrict__ q, const float* __restrict__ s,
                       const float* __restrict__ in) {
    int bid = blockIdx.x;
    int tid = threadIdx.x;
    if (bid < NWB) {
        __shared__ float t[32][33];
        int n0 = (bid & 127) * 32, k0 = (bid >> 7) * 32;
        int tx = tid & 31, ty = tid >> 5;     // 32 x 8
        int sb = n0 >> 5;
#pragma unroll
        for (int i = 0; i < 4; i++) {
            int k = k0 + ty + i * 8;
            t[ty + i * 8][tx] = (float)q[(size_t)k * Ndim + n0 + tx]
                              * s[(size_t)k * (Ndim / 32) + sb];
        }
        __syncthreads();
        int itx = ileave16(tx);
#pragma unroll
        for (int i = 0; i < 4; i++)
            g_wt[(size_t)(n0 + ty + i * 8) * Kdim + k0 + itx] =
                __float2half_rn(t[tx][ty + i * 8]);
    } else {
        size_t idx = (size_t)(bid - NWB) * 256 + tid;   // one 16-k group / thread
        size_t m = idx >> 8;
        int g = (int)(idx & 255);
        const float* p = in + m * Kdim + g * 16;
        uint32_t w[8];
#pragma unroll
        for (int sl = 0; sl < 8; sl++) {
            int pp = (sl >> 1) + ((sl & 1) << 2);
            __half2 h = __floats2half2_rn(p[2 * pp], p[2 * pp + 1]);
            w[sl] = *reinterpret_cast<uint32_t*>(&h);
        }
        uint4* dst = reinterpret_cast<uint4*>(g_a + m * Kdim + g * 16);
        dst[0] = make_uint4(w[0], w[1], w[2], w[3]);
        dst[1] = make_uint4(w[4], w[5], w[6], w[7]);
    }
}

// ---------- GEMM: fp16 m16n8k16, 256x128x32 CTA, 256 thr, warp 64x64, 5-stage ----------
DI void load_tile(uint32_t sb, int tid, int m0, int n0, int jt, int s) {
    const __half* Ap = g_a  + (size_t)m0 * Kdim + jt * KT;
    const __half* Bp = g_wt + (size_t)n0 * Kdim + jt * KT;
    uint32_t base = sb + (uint32_t)s * STG;
#pragma unroll
    for (int i = 0; i < 6; i++) {
        int idx = tid + i * 256;                 // 0..1535
        if (idx < 1024) {                        // A: 256 rows x 4 chunks of 16B
            int r = idx >> 2, c = idx & 3;
            cpa16(base + (uint32_t)(r * ROWB + c * 16), Ap + (size_t)r * Kdim + c * 8);
        } else {                                 // B: 128 rows x 4 chunks
            int j = idx - 1024;
            int r = j >> 2, c = j & 3;
            cpa16(base + TILE_A + (uint32_t)(r * ROWB + c * 16), Bp + (size_t)r * Kdim + c * 8);
        }
    }
    cpa_commit();
}

__global__ void __launch_bounds__(256, 1) gemm_k(const float* __restrict__ bias,
                                                 float* __restrict__ out) {
    extern __shared__ __align__(1024) char smem[];
    uint32_t sb = smem_u32(smem);
    int tid = threadIdx.x, wid = tid >> 5, lane = tid & 31;
    int qr = lane >> 2, qt = lane & 3;
    int wm = wid >> 1, wn = wid & 1;            // 4 x 2 warp grid, 64x64 warp tile
    int n0 = blockIdx.x * NT, m0 = blockIdx.y * MT;
    int rA = wm * 64 + qr;
    int rB = wn * 64 + qr;

    float acc[4][8][4];
#pragma unroll
    for (int a = 0; a < 4; a++)
#pragma unroll
        for (int b = 0; b < 8; b++)
#pragma unroll
            for (int c = 0; c < 4; c++) acc[a][b][c] = 0.f;

    load_tile(sb, tid, m0, n0, 0, 0);
    load_tile(sb, tid, m0, n0, 1, 1);
    load_tile(sb, tid, m0, n0, 2, 2);
    load_tile(sb, tid, m0, n0, 3, 3);

    int s = 0, sl = 4;                          // compute stage, next load stage
    for (int jt = 0; jt < NKT; ++jt) {
        int rem = NKT - jt - 1;                 // pending groups beyond current
        if (rem >= 3)      cpa_wait<3>();
        else if (rem == 2) cpa_wait<2>();
        else if (rem == 1) cpa_wait<1>();
        else               cpa_wait<0>();
        __syncthreads();

        const uint2* As2 = (const uint2*)(smem + (size_t)s * STG) + (size_t)rA * RP8;
        const uint2* Bs2 = (const uint2*)(smem + (size_t)s * STG + TILE_A) + (size_t)rB * RP8;

#pragma unroll
        for (int ks = 0; ks < 2; ++ks) {
            int co = ks * 4 + qt;
            uint2 a02[4], a13[4], bb[8];
#pragma unroll
            for (int mi = 0; mi < 4; ++mi) {
                a02[mi] = As2[(mi * 16)     * RP8 + co];
                a13[mi] = As2[(mi * 16 + 8) * RP8 + co];
            }
#pragma unroll
            for (int ni = 0; ni < 8; ++ni)
                bb[ni] = Bs2[(ni * 8) * RP8 + co];
#pragma unroll
            for (int mi = 0; mi < 4; ++mi)
#pragma unroll
                for (int ni = 0; ni < 8; ++ni)
                    mma16(acc[mi][ni], a02[mi].x, a13[mi].x, a02[mi].y, a13[mi].y,
                          bb[ni].x, bb[ni].y);
        }
        if (jt + 4 < NKT) {
            load_tile(sb, tid, m0, n0, jt + 4, sl);
            if (++sl == NSTG) sl = 0;
        }
        if (++s == NSTG) s = 0;
    }

#pragma unroll
    for (int mi = 0; mi < 4; ++mi) {
        int r0 = m0 + wm * 64 + mi * 16 + qr;
#pragma unroll
        for (int ni = 0; ni < 8; ++ni) {
            int n = n0 + wn * 64 + ni * 8 + 2 * qt;
            float b0 = bias[n], b1 = bias[n + 1];
            float2 v0 = {acc[mi][ni][0] + b0, acc[mi][ni][1] + b1};
            float2 v1 = {acc[mi][ni][2] + b0, acc[mi][ni][3] + b1};
            *reinterpret_cast<float2*>(out + (size_t)r0 * Ndim + n) = v0;
            *reinterpret_cast<float2*>(out + (size_t)(r0 + 8) * Ndim + n) = v1;
        }
    }
}

extern "C" void kernel_launch(void* const* d_in, const int* in_sizes, int n_in,
                              void* d_out, int out_size) {
    const float* inp  = (const float*)d_in[0];
    const int*   qw   = (const int*)d_in[1];
    const float* sc   = (const float*)d_in[2];
    const float* bias = (const float*)d_in[3];
    float* out = (float*)d_out;

    cudaFuncSetAttribute(gemm_k, cudaFuncAttributeMaxDynamicSharedMemorySize, SMEM_BYTES);

    prep_k<<<NWB + NAB, 256>>>(qw, sc, inp);
    gemm_k<<<dim3(Ndim / NT, Mdim / MT), 256, SMEM_BYTES>>>(bias, out);
}

// round 9
// speedup vs baseline: 1.0006x; 1.0006x over previous
#include <cuda_runtime.h>
#include <cuda_fp16.h>
#include <cstdint>
#include <cstddef>

#define DI __device__ __forceinline__

static constexpr int Mdim = 8192, Ndim = 4096, Kdim = 4096;
static constexpr int MT = 256, NT = 128, KT = 64;
static constexpr int NKT = Kdim / KT;              // 64
static constexpr int ROWB = 160;                   // row stride bytes (128B data + 32B pad)
static constexpr int RP8 = ROWB / 8;               // 20
static constexpr int TILE_A = 256 * ROWB;          // 40960 B
static constexpr int TILE_B = 128 * ROWB;          // 20480 B
static constexpr int STG = TILE_A + TILE_B;        // 61440 B
static constexpr unsigned SMEM_BYTES = 3 * STG;    // 184320

// fp16, k-interleaved within each 16-k group: word slots [k0k1 k8k9 k2k3 k10k11 k4k5 k12k13 k6k7 k14k15]
__device__ __half g_wt[(size_t)Ndim * Kdim];       // W^T [n][k]
__device__ __half g_a [(size_t)Mdim * Kdim];       // A   [m][k]

DI uint32_t smem_u32(const void* p) {
    uint32_t a;
    asm("{ .reg .u64 t; cvta.to.shared.u64 t, %1; cvt.u32.u64 %0, t; }" : "=r"(a) : "l"(p));
    return a;
}
DI void cpa16(uint32_t dst, const void* src) {
    asm volatile("cp.async.cg.shared.global [%0], [%1], 16;" :: "r"(dst), "l"(src) : "memory");
}
DI void cpa_commit() { asm volatile("cp.async.commit_group;" ::: "memory"); }
template <int N> DI void cpa_wait() {
    asm volatile("cp.async.wait_group %0;" :: "n"(N) : "memory");
}
DI void mma16(float* d, uint32_t a0, uint32_t a1, uint32_t a2, uint32_t a3,
              uint32_t b0, uint32_t b1) {
    asm volatile(
        "mma.sync.aligned.m16n8k16.row.col.f32.f16.f16.f32 "
        "{%0,%1,%2,%3}, {%4,%5,%6,%7}, {%8,%9}, {%0,%1,%2,%3};"
        : "+f"(d[0]), "+f"(d[1]), "+f"(d[2]), "+f"(d[3])
        : "r"(a0), "r"(a1), "r"(a2), "r"(a3), "r"(b0), "r"(b1));
}
DI int ileave16(int e) {
    int p = (e >> 1) & 7, o = e & 1;
    int slot = ((p & 3) << 1) | (p >> 2);
    return (e & ~15) | (slot << 1) | o;
}

// ---------- prep 1: g_wt[n][ik] = fp16(q[k][n]*s[k][n/32]), transposed + interleaved ----------
__global__ void dequant_k(const int* __restrict__ q, const float* __restrict__ s) {
    __shared__ float t[32][33];
    int n0 = blockIdx.x * 32, k0 = blockIdx.y * 32;
    int tx = threadIdx.x, ty = threadIdx.y;   // 32 x 8
    int sb = n0 >> 5;
#pragma unroll
    for (int i = 0; i < 4; i++) {
        int k = k0 + ty + i * 8;
        t[ty + i * 8][tx] = (float)q[(size_t)k * Ndim + n0 + tx] * s[(size_t)k * (Ndim / 32) + sb];
    }
    __syncthreads();
    int itx = ileave16(tx);
#pragma unroll
    for (int i = 0; i < 4; i++)
        g_wt[(size_t)(n0 + ty + i * 8) * Kdim + k0 + itx] = __float2half_rn(t[tx][ty + i * 8]);
}

// ---------- prep 2: A f32 -> fp16 + interleave (one 16-k group per thread) ----------
__global__ void round_a_k(const float* __restrict__ in) {
    size_t idx = (size_t)blockIdx.x * blockDim.x + threadIdx.x;  // M*K/16
    size_t m = idx >> 8;                   // K/16 = 256 groups per row
    int g = (int)(idx & 255);
    const float* p = in + m * Kdim + g * 16;
    uint32_t w[8];
#pragma unroll
    for (int s = 0; s < 8; s++) {
        int pp = (s >> 1) + ((s & 1) << 2);
        __half2 h = __floats2half2_rn(p[2 * pp], p[2 * pp + 1]);
        w[s] = *reinterpret_cast<uint32_t*>(&h);
    }
    uint4* dst = reinterpret_cast<uint4*>(g_a + m * Kdim + g * 16);
    dst[0] = make_uint4(w[0], w[1], w[2], w[3]);
    dst[1] = make_uint4(w[4], w[5], w[6], w[7]);
}

// ---------- GEMM: fp16 m16n8k16, 256x128x64 CTA, 256 thr, warp 64x64, 3-stage ----------
DI void load_tile(uint32_t sb, int tid, int m0, int n0, int jt, int s) {
    const __half* Ap = g_a  + (size_t)m0 * Kdim + jt * KT;
    const __half* Bp = g_wt + (size_t)n0 * Kdim + jt * KT;
    uint32_t base = sb + (uint32_t)s * STG;
#pragma unroll
    for (int i = 0; i < 12; i++) {
        int idx = tid + i * 256;                 // 0..3071
        if (idx < 2048) {                        // A: 256 rows x 8 chunks of 16B
            int r = idx >> 3, c = idx & 7;
            cpa16(base + (uint32_t)(r * ROWB + c * 16), Ap + (size_t)r * Kdim + c * 8);
        } else {                                 // B: 128 rows x 8 chunks
            int j = idx - 2048;
            int r = j >> 3, c = j & 7;
            cpa16(base + TILE_A + (uint32_t)(r * ROWB + c * 16), Bp + (size_t)r * Kdim + c * 8);
        }
    }
    cpa_commit();
}

__global__ void __launch_bounds__(256, 1) gemm_k(const float* __restrict__ bias,
                                                 float* __restrict__ out) {
    extern __shared__ __align__(1024) char smem[];
    uint32_t sb = smem_u32(smem);
    int tid = threadIdx.x, wid = tid >> 5, lane = tid & 31;
    int qr = lane >> 2, qt = lane & 3;
    int wm = wid >> 1, wn = wid & 1;            // 4 x 2 warp grid, 64x64 warp tile
    int n0 = blockIdx.x * NT, m0 = blockIdx.y * MT;
    int rA = wm * 64 + qr;
    int rB = wn * 64 + qr;

    float acc[4][8][4];
#pragma unroll
    for (int a = 0; a < 4; a++)
#pragma unroll
        for (int b = 0; b < 8; b++)
#pragma unroll
            for (int c = 0; c < 4; c++) acc[a][b][c] = 0.f;

    load_tile(sb, tid, m0, n0, 0, 0);
    load_tile(sb, tid, m0, n0, 1, 1);

    uint2 a02[2][4], a13[2][4], bb[2][8];       // double-buffered fragments

    int s = 0;
    for (int jt = 0; jt < NKT; ++jt) {
        if (jt + 1 < NKT) cpa_wait<1>(); else cpa_wait<0>();
        __syncthreads();
        if (jt + 2 < NKT) load_tile(sb, tid, m0, n0, jt + 2, (jt + 2) % 3);

        const uint2* As2 = (const uint2*)(smem + (size_t)s * STG) + (size_t)rA * RP8;
        const uint2* Bs2 = (const uint2*)(smem + (size_t)s * STG + TILE_A) + (size_t)rB * RP8;

        auto ldfr = [&](int buf, int co) {
#pragma unroll
            for (int mi = 0; mi < 4; ++mi) {
                a02[buf][mi] = As2[(mi * 16)     * RP8 + co];
                a13[buf][mi] = As2[(mi * 16 + 8) * RP8 + co];
            }
#pragma unroll
            for (int ni = 0; ni < 8; ++ni)
                bb[buf][ni] = Bs2[(ni * 8) * RP8 + co];
        };

        ldfr(0, qt);                            // ks = 0 fragments
#pragma unroll
        for (int ks = 0; ks < 4; ++ks) {
            int cur = ks & 1;
            if (ks < 3) ldfr(cur ^ 1, (ks + 1) * 4 + qt);   // prefetch next ks
#pragma unroll
            for (int mi = 0; mi < 4; ++mi)
#pragma unroll
                for (int ni = 0; ni < 8; ++ni)
                    mma16(acc[mi][ni],
                          a02[cur][mi].x, a13[cur][mi].x, a02[cur][mi].y, a13[cur][mi].y,
                          bb[cur][ni].x, bb[cur][ni].y);
        }
        if (++s == 3) s = 0;
    }

#pragma unroll
    for (int mi = 0; mi < 4; ++mi) {
        int r0 = m0 + wm * 64 + mi * 16 + qr;
#pragma unroll
        for (int ni = 0; ni < 8; ++ni) {
            int n = n0 + wn * 64 + ni * 8 + 2 * qt;
            float b0 = bias[n], b1 = bias[n + 1];
            float2 v0 = {acc[mi][ni][0] + b0, acc[mi][ni][1] + b1};
            float2 v1 = {acc[mi][ni][2] + b0, acc[mi][ni][3] + b1};
            *reinterpret_cast<float2*>(out + (size_t)r0 * Ndim + n) = v0;
            *reinterpret_cast<float2*>(out + (size_t)(r0 + 8) * Ndim + n) = v1;
        }
    }
}

extern "C" void kernel_launch(void* const* d_in, const int* in_sizes, int n_in,
                              void* d_out, int out_size) {
    const float* inp  = (const float*)d_in[0];
    const int*   qw   = (const int*)d_in[1];
    const float* sc   = (const float*)d_in[2];
    const float* bias = (const float*)d_in[3];
    float* out = (float*)d_out;

    cudaFuncSetAttribute(gemm_k, cudaFuncAttributeMaxDynamicSharedMemorySize, SMEM_BYTES);

    dequant_k<<<dim3(Ndim / 32, Kdim / 32), dim3(32, 8)>>>(qw, sc);
    round_a_k<<<(int)((size_t)Mdim * Kdim / 16 / 256), 256>>>(inp);
    gemm_k<<<dim3(Ndim / NT, Mdim / MT), 256, SMEM_BYTES>>>(bias, out);
}

// round 10
// speedup vs baseline: 1.0968x; 1.0960x over previous
#include <cuda_runtime.h>
#include <cuda_fp16.h>
#include <cstdint>
#include <cstddef>

#define DI __device__ __forceinline__

static constexpr int Mdim = 8192, Ndim = 4096, Kdim = 4096;
static constexpr int MT = 128, NT = 128, KT = 64;
static constexpr int NKT = Kdim / KT;              // 64
static constexpr int ROWB = 160;                   // row stride bytes (128B data + 32B pad)
static constexpr int RP8 = ROWB / 8;               // 20
static constexpr int TILE_A = 128 * ROWB;          // 20480 B
static constexpr int TILE_B = 128 * ROWB;          // 20480 B
static constexpr int STG = TILE_A + TILE_B;        // 40960 B
static constexpr unsigned SMEM_BYTES = 2 * STG;    // 81920 (x2 CTAs = 160KB/SM)

// fp16, k-interleaved within each 16-k group: word slots [k0k1 k8k9 k2k3 k10k11 k4k5 k12k13 k6k7 k14k15]
__device__ __half g_wt[(size_t)Ndim * Kdim];       // W^T [n][k]
__device__ __half g_a [(size_t)Mdim * Kdim];       // A   [m][k]

DI uint32_t smem_u32(const void* p) {
    uint32_t a;
    asm("{ .reg .u64 t; cvta.to.shared.u64 t, %1; cvt.u32.u64 %0, t; }" : "=r"(a) : "l"(p));
    return a;
}
DI void cpa16(uint32_t dst, const void* src) {
    asm volatile("cp.async.cg.shared.global [%0], [%1], 16;" :: "r"(dst), "l"(src) : "memory");
}
DI void cpa_commit() { asm volatile("cp.async.commit_group;" ::: "memory"); }
template <int N> DI void cpa_wait() {
    asm volatile("cp.async.wait_group %0;" :: "n"(N) : "memory");
}
DI void mma16(float* d, uint32_t a0, uint32_t a1, uint32_t a2, uint32_t a3,
              uint32_t b0, uint32_t b1) {
    asm volatile(
        "mma.sync.aligned.m16n8k16.row.col.f32.f16.f16.f32 "
        "{%0,%1,%2,%3}, {%4,%5,%6,%7}, {%8,%9}, {%0,%1,%2,%3};"
        : "+f"(d[0]), "+f"(d[1]), "+f"(d[2]), "+f"(d[3])
        : "r"(a0), "r"(a1), "r"(a2), "r"(a3), "r"(b0), "r"(b1));
}
DI int ileave16(int e) {
    int p = (e >> 1) & 7, o = e & 1;
    int slot = ((p & 3) << 1) | (p >> 2);
    return (e & ~15) | (slot << 1) | o;
}

// ---------- prep 1: g_wt[n][ik] = fp16(q[k][n]*s[k][n/32]), transposed + interleaved ----------
__global__ void dequant_k(const int* __restrict__ q, const float* __restrict__ s) {
    __shared__ float t[32][33];
    int n0 = blockIdx.x * 32, k0 = blockIdx.y * 32;
    int tx = threadIdx.x, ty = threadIdx.y;   // 32 x 8
    int sb = n0 >> 5;
#pragma unroll
    for (int i = 0; i < 4; i++) {
        int k = k0 + ty + i * 8;
        t[ty + i * 8][tx] = (float)q[(size_t)k * Ndim + n0 + tx] * s[(size_t)k * (Ndim / 32) + sb];
    }
    __syncthreads();
    int itx = ileave16(tx);
#pragma unroll
    for (int i = 0; i < 4; i++)
        g_wt[(size_t)(n0 + ty + i * 8) * Kdim + k0 + itx] = __float2half_rn(t[tx][ty + i * 8]);
}

// ---------- prep 2: A f32 -> fp16 + interleave (one 16-k group per thread) ----------
__global__ void round_a_k(const float* __restrict__ in) {
    size_t idx = (size_t)blockIdx.x * blockDim.x + threadIdx.x;  // M*K/16
    size_t m = idx >> 8;                   // K/16 = 256 groups per row
    int g = (int)(idx & 255);
    const float* p = in + m * Kdim + g * 16;
    uint32_t w[8];
#pragma unroll
    for (int s = 0; s < 8; s++) {
        int pp = (s >> 1) + ((s & 1) << 2);
        __half2 h = __floats2half2_rn(p[2 * pp], p[2 * pp + 1]);
        w[s] = *reinterpret_cast<uint32_t*>(&h);
    }
    uint4* dst = reinterpret_cast<uint4*>(g_a + m * Kdim + g * 16);
    dst[0] = make_uint4(w[0], w[1], w[2], w[3]);
    dst[1] = make_uint4(w[4], w[5], w[6], w[7]);
}

// ---------- GEMM: fp16 m16n8k16, 128x128x64 CTA, 128 thr, warp 64x64, 2 CTA/SM ----------
DI void load_tile(uint32_t sb, int tid, int m0, int n0, int jt, int s) {
    const __half* Ap = g_a  + (size_t)m0 * Kdim + jt * KT;
    const __half* Bp = g_wt + (size_t)n0 * Kdim + jt * KT;
    uint32_t base = sb + (uint32_t)s * STG;
#pragma unroll
    for (int i = 0; i < 16; i++) {
        int idx = tid + i * 128;                 // 0..2047
        int half = idx >> 10;                    // 0 = A, 1 = B
        int j = idx & 1023;
        int r = j >> 3, c = j & 7;               // row 0..127, 16B chunk 0..7
        const __half* src = (half ? Bp : Ap) + (size_t)r * Kdim + c * 8;
        cpa16(base + (uint32_t)half * TILE_A + (uint32_t)(r * ROWB + c * 16), src);
    }
    cpa_commit();
}

__global__ void __launch_bounds__(128, 2) gemm_k(const float* __restrict__ bias,
                                                 float* __restrict__ out) {
    extern __shared__ __align__(1024) char smem[];
    uint32_t sb = smem_u32(smem);
    int tid = threadIdx.x, wid = tid >> 5, lane = tid & 31;
    int qr = lane >> 2, qt = lane & 3;
    int wm = wid >> 1, wn = wid & 1;            // 2 x 2 warp grid, 64x64 warp tile
    int n0 = blockIdx.x * NT, m0 = blockIdx.y * MT;
    int rA = wm * 64 + qr;
    int rB = wn * 64 + qr;

    float acc[4][8][4];
#pragma unroll
    for (int a = 0; a < 4; a++)
#pragma unroll
        for (int b = 0; b < 8; b++)
#pragma unroll
            for (int c = 0; c < 4; c++) acc[a][b][c] = 0.f;

    load_tile(sb, tid, m0, n0, 0, 0);

    for (int jt = 0; jt < NKT; ++jt) {
        cpa_wait<0>();                          // tile jt resident
        __syncthreads();                        // everyone done with the other stage
        if (jt + 1 < NKT)                       // prefetch next into the freed stage
            load_tile(sb, tid, m0, n0, jt + 1, (jt + 1) & 1);

        int s = jt & 1;
        const uint2* As2 = (const uint2*)(smem + (size_t)s * STG) + (size_t)rA * RP8;
        const uint2* Bs2 = (const uint2*)(smem + (size_t)s * STG + TILE_A) + (size_t)rB * RP8;

#pragma unroll
        for (int ks = 0; ks < 4; ++ks) {
            int co = ks * 4 + qt;
            uint2 a02[4], a13[4], bb[8];
#pragma unroll
            for (int mi = 0; mi < 4; ++mi) {
                a02[mi] = As2[(mi * 16)     * RP8 + co];
                a13[mi] = As2[(mi * 16 + 8) * RP8 + co];
            }
#pragma unroll
            for (int ni = 0; ni < 8; ++ni)
                bb[ni] = Bs2[(ni * 8) * RP8 + co];
#pragma unroll
            for (int mi = 0; mi < 4; ++mi)
#pragma unroll
                for (int ni = 0; ni < 8; ++ni)
                    mma16(acc[mi][ni], a02[mi].x, a13[mi].x, a02[mi].y, a13[mi].y,
                          bb[ni].x, bb[ni].y);
        }
        __syncthreads();                        // readers done before next overwrite
    }

#pragma unroll
    for (int mi = 0; mi < 4; ++mi) {
        int r0 = m0 + wm * 64 + mi * 16 + qr;
#pragma unroll
        for (int ni = 0; ni < 8; ++ni) {
            int n = n0 + wn * 64 + ni * 8 + 2 * qt;
            float b0 = bias[n], b1 = bias[n + 1];
            float2 v0 = {acc[mi][ni][0] + b0, acc[mi][ni][1] + b1};
            float2 v1 = {acc[mi][ni][2] + b0, acc[mi][ni][3] + b1};
            *reinterpret_cast<float2*>(out + (size_t)r0 * Ndim + n) = v0;
            *reinterpret_cast<float2*>(out + (size_t)(r0 + 8) * Ndim + n) = v1;
        }
    }
}

extern "C" void kernel_launch(void* const* d_in, const int* in_sizes, int n_in,
                              void* d_out, int out_size) {
    const float* inp  = (const float*)d_in[0];
    const int*   qw   = (const int*)d_in[1];
    const float* sc   = (const float*)d_in[2];
    const float* bias = (const float*)d_in[3];
    float* out = (float*)d_out;

    cudaFuncSetAttribute(gemm_k, cudaFuncAttributeMaxDynamicSharedMemorySize, SMEM_BYTES);

    dequant_k<<<dim3(Ndim / 32, Kdim / 32), dim3(32, 8)>>>(qw, sc);
    round_a_k<<<(int)((size_t)Mdim * Kdim / 16 / 256), 256>>>(inp);
    gemm_k<<<dim3(Ndim / NT, Mdim / MT), 128, SMEM_BYTES>>>(bias, out);
}